// round 7
// baseline (speedup 1.0000x reference)
#include <cuda_runtime.h>
#include <cuda_bf16.h>

#define NPTS 1024
#define KPOS 512
#define KSEL 32
#define FULLMASK 0xFFFFFFFFu
#define NCHUNK 8

typedef unsigned long long ull;

// scratch: compacted selected points per submap (x,y,z,idx-bits) + FPS seed slot
__device__ float4 g_pts[2048 * KPOS];
__device__ int    g_seed[2048];

// ---- packed f32x2 helpers (lanewise IEEE rn — bit-identical to scalar rn ops)
__device__ __forceinline__ ull pk2(float a, float b) {
    ull r; asm("mov.b64 %0, {%1, %2};" : "=l"(r) : "f"(a), "f"(b)); return r;
}
__device__ __forceinline__ void upk2(ull v, float& a, float& b) {
    asm("mov.b64 {%0, %1}, %2;" : "=f"(a), "=f"(b) : "l"(v));
}
__device__ __forceinline__ ull addx2(ull a, ull b) {
    ull r; asm("add.rn.f32x2 %0, %1, %2;" : "=l"(r) : "l"(a), "l"(b)); return r;
}
__device__ __forceinline__ ull mulx2(ull a, ull b) {
    ull r; asm("mul.rn.f32x2 %0, %1, %2;" : "=l"(r) : "l"(a), "l"(b)); return r;
}

// ============================================================================
// Kernel 1: per-submap selection of the 512 xy-closest points (exact jax
// top_k(-dist) semantics incl. ties). Radix select + closed-form compaction.
// ============================================================================
__global__ __launch_bounds__(1024, 2)
void select_kernel(const float* __restrict__ pos, int b0)
{
    __shared__ unsigned int hist[2048];
    __shared__ unsigned int sstate[2];   // [0]=prefix/T  [1]=kth/r
    __shared__ unsigned int wA[32], wB[32];
    __shared__ ull wpk[32];
    __shared__ ull spk;

    const int t = threadIdx.x;
    const int w = t >> 5, lane = t & 31;
    const int b = b0 + blockIdx.x;
    const long base = (long)b * NPTS;

    if (t == 0) { sstate[0] = 0u; sstate[1] = KPOS; }

    // ---- per-point key: sqrt(px^2+py^2), non-fused (match XLA) ----
    const float px = pos[3*(base+t)+0];
    const float py = pos[3*(base+t)+1];
    const float pz = pos[3*(base+t)+2];
    const unsigned int kb =
        __float_as_uint(__fsqrt_rn(__fadd_rn(__fmul_rn(px,px), __fmul_rn(py,py))));

    // ---- radix select KPOS-th smallest: 3 passes (11/11/10 bits) ----
    {
        const int shifts[3] = {21, 10, 0};
        const int bitsv [3] = {11, 11, 10};
        #pragma unroll 1
        for (int p = 0; p < 3; p++) {
            const int shift = shifts[p];
            const int nb = 1 << bitsv[p];
            hist[t] = 0u; hist[t + 1024] = 0u;
            __syncthreads();
            const unsigned int prefix = sstate[0], kth = sstate[1];
            const int sb = shift + bitsv[p];
            const unsigned int hm = (sb >= 32) ? 0u : (0xFFFFFFFFu << sb);
            if ((kb & hm) == prefix)
                atomicAdd(&hist[(kb >> shift) & (nb - 1)], 1u);
            __syncthreads();

            // parallel prefix over 2048 bins: thread owns bins {2t, 2t+1}
            const unsigned int h0 = hist[2 * t];
            const unsigned int h1 = hist[2 * t + 1];
            const unsigned int s = h0 + h1;
            unsigned int inc = s;
            #pragma unroll
            for (int d = 1; d < 32; d <<= 1) {
                unsigned int v = __shfl_up_sync(FULLMASK, inc, d);
                if (lane >= d) inc += v;
            }
            if (lane == 31) wA[w] = inc;
            __syncthreads();
            if (t < 32) {
                unsigned int wv = wA[t];
                unsigned int winc = wv;
                #pragma unroll
                for (int d = 1; d < 32; d <<= 1) {
                    unsigned int v = __shfl_up_sync(FULLMASK, winc, d);
                    if (t >= d) winc += v;
                }
                wA[t] = winc - wv;
            }
            __syncthreads();
            const unsigned int base0 = wA[w] + (inc - s);
            if (kth > base0 && kth <= base0 + h0) {
                sstate[0] = prefix | ((unsigned int)(2 * t) << shift);
                sstate[1] = kth - base0;
            } else if (kth > base0 + h0 && kth <= base0 + h0 + h1) {
                sstate[0] = prefix | ((unsigned int)(2 * t + 1) << shift);
                sstate[1] = kth - base0 - h0;
            }
            __syncthreads();
        }
    }
    const unsigned int T = sstate[0];
    const unsigned int r = sstate[1];

    // ---- closed-form tie handling + compaction + seed, 2 barriers total ----
    const bool ltT  = (kb < T);
    const bool tied = (kb == T);
    const unsigned int balL = __ballot_sync(FULLMASK, ltT);
    const unsigned int balT = __ballot_sync(FULLMASK, tied);
    if (lane == 0) { wA[w] = __popc(balL); wB[w] = __popc(balT); }

    ull pk = (((ull)kb) << 32) | (unsigned int)t;
    #pragma unroll
    for (int off = 16; off > 0; off >>= 1) {
        ull o2 = __shfl_xor_sync(FULLMASK, pk, off);
        if (o2 < pk) pk = o2;
    }
    if (lane == 0) wpk[w] = pk;
    __syncthreads();
    if (t < 32) {
        unsigned int a0 = wA[t], b0v = wB[t];
        unsigned int ia = a0, ib = b0v;
        #pragma unroll
        for (int d = 1; d < 32; d <<= 1) {
            unsigned int va = __shfl_up_sync(FULLMASK, ia, d);
            unsigned int vb = __shfl_up_sync(FULLMASK, ib, d);
            if (t >= d) { ia += va; ib += vb; }
        }
        wA[t] = ia - a0; wB[t] = ib - b0v;

        ull v2 = wpk[t];
        #pragma unroll
        for (int off = 16; off > 0; off >>= 1) {
            ull o2 = __shfl_xor_sync(FULLMASK, v2, off);
            if (o2 < v2) v2 = o2;
        }
        if (t == 0) spk = v2;
    }
    __syncthreads();
    const unsigned int lm = (1u << lane) - 1u;
    const unsigned int cnt_lt = wA[w] + __popc(balL & lm);
    const unsigned int cnt_td = wB[w] + __popc(balT & lm);
    const bool sel = ltT || (tied && cnt_td < r);
    if (sel) {
        const int slot = (int)(cnt_lt + (cnt_td < r ? cnt_td : r));
        g_pts[b * KPOS + slot] = make_float4(px, py, pz, __int_as_float(t));
        if ((unsigned int)t == (unsigned int)(spk & 0xFFFFFFFFull))
            g_seed[b] = slot;
    }
}

// ============================================================================
// Kernel 2: TWO warps per submap (8 pts/lane in regs, packed f32x2 updates).
// Cross-warp argmax: 1 named barrier/step + double-buffered smem slot.
// Block = 128 threads = 2 submaps; warp0 of each pair runs the MLP.
// ============================================================================
__global__ __launch_bounds__(128)
void fps_mlp_kernel(const float* __restrict__ x,
                    const float* __restrict__ W1, const float* __restrict__ b1,
                    const float* __restrict__ W2, const float* __restrict__ b2,
                    const float* __restrict__ W3, const float* __restrict__ b3,
                    float* __restrict__ out_w, float* __restrict__ out_i, int b0)
{
    __shared__ float4 qpos[2 * KPOS];
    __shared__ ull xw[2][2][2];   // [pair][buf][warp-in-pair]
    __shared__ float sW1[512]; __shared__ float sb1[16];
    __shared__ float sW2[128]; __shared__ float sb2[8];
    __shared__ float sW3[8];   __shared__ float sb3v;

    const int tid = threadIdx.x;
    for (int i = tid; i < 512; i += 128) sW1[i] = W1[i];
    if (tid < 128) sW2[tid] = W2[tid];
    if (tid < 16)  sb1[tid] = b1[tid];
    if (tid < 8)   sb2[tid] = b2[tid];
    if (tid < 8)   sW3[tid] = W3[tid];
    if (tid == 0)  sb3v = b3[0];
    __syncthreads();

    const int w = tid >> 5, lane = tid & 31;
    const int pair = w >> 1, ww = w & 1;
    const int b = b0 + blockIdx.x * 2 + pair;
    const int barid = 1 + pair;
    const int pbase = ww * 32 + lane;   // this lane's slot stride base

    const float4* bp = g_pts + (size_t)b * KPOS;
    float4* qp = qpos + pair * KPOS;

    ull pxp[4], pyp[4], pzp[4];
    float md[8];
    #pragma unroll
    for (int k = 0; k < 4; k++) {
        const float4 v0 = bp[(2*k)     * 64 + pbase];
        const float4 v1 = bp[(2*k + 1) * 64 + pbase];
        qp[(2*k)     * 64 + pbase] = v0;
        qp[(2*k + 1) * 64 + pbase] = v1;
        pxp[k] = pk2(v0.x, v1.x);
        pyp[k] = pk2(v0.y, v1.y);
        pzp[k] = pk2(v0.z, v1.z);
    }
    asm volatile("bar.sync %0, %1;" :: "r"(barid), "r"(64) : "memory");

    const int s0 = g_seed[b];
    float4 q = qp[s0];
    int mysel = s0;   // warp0 lane 'step' records the step'th selection

    {
        const ull qnx = pk2(-q.x, -q.x), qny = pk2(-q.y, -q.y), qnz = pk2(-q.z, -q.z);
        #pragma unroll
        for (int k = 0; k < 4; k++) {
            const ull dx = addx2(pxp[k], qnx);
            const ull dy = addx2(pyp[k], qny);
            const ull dz = addx2(pzp[k], qnz);
            const ull d2 = addx2(addx2(mulx2(dx,dx), mulx2(dy,dy)), mulx2(dz,dz));
            upk2(d2, md[2*k], md[2*k+1]);
        }
    }

    #pragma unroll 1
    for (int step = 1; step < KSEL; step++) {
        float best = md[0]; int bs = pbase;
        #pragma unroll
        for (int j = 1; j < 8; j++) {
            const int s = j * 64 + pbase;
            if (md[j] > best) { best = md[j]; bs = s; }
        }
        const unsigned int bb = __float_as_uint(best);
        const unsigned int wm = __reduce_max_sync(FULLMASK, bb);
        const unsigned int cand = (bb == wm) ? (unsigned int)bs : 0xFFFFFFFFu;
        const unsigned int ws = __reduce_min_sync(FULLMASK, cand);
        const int buf = step & 1;
        if (lane == 0)
            xw[pair][buf][ww] = (((ull)wm) << 32) | (unsigned int)(~ws);
        asm volatile("bar.sync %0, %1;" :: "r"(barid), "r"(64) : "memory");
        const ull p0 = xw[pair][buf][0];
        const ull p1 = xw[pair][buf][1];
        const ull win = (p0 > p1) ? p0 : p1;   // max dist, tie -> min slot
        const int cur = (int)(~(unsigned int)(win & 0xFFFFFFFFull));
        if (ww == 0 && lane == step) mysel = cur;
        q = qp[cur];
        const ull qnx = pk2(-q.x, -q.x), qny = pk2(-q.y, -q.y), qnz = pk2(-q.z, -q.z);
        #pragma unroll
        for (int k = 0; k < 4; k++) {
            const ull dx = addx2(pxp[k], qnx);
            const ull dy = addx2(pyp[k], qny);
            const ull dz = addx2(pzp[k], qnz);
            const ull d2 = addx2(addx2(mulx2(dx,dx), mulx2(dy,dy)), mulx2(dz,dz));
            float a, c2;
            upk2(d2, a, c2);
            md[2*k]   = fminf(md[2*k],   a);
            md[2*k+1] = fminf(md[2*k+1], c2);
        }
    }

    // ---- per-lane MLP (warp0 of each pair; lane = selection step) ----
    if (ww == 0) {
        const float4 qs = qp[mysel];
        const int o = __float_as_int(qs.w);
        const float* xr = x + ((long)b * NPTS + o) * 32;

        float h1[16];
        #pragma unroll
        for (int k2 = 0; k2 < 16; k2++) h1[k2] = sb1[k2];
        #pragma unroll
        for (int i = 0; i < 32; i += 4) {
            const float4 xv = *(const float4*)(xr + i);
            #pragma unroll
            for (int k2 = 0; k2 < 16; k2++) {
                h1[k2] = fmaf(xv.x, sW1[(i+0) * 16 + k2], h1[k2]);
                h1[k2] = fmaf(xv.y, sW1[(i+1) * 16 + k2], h1[k2]);
                h1[k2] = fmaf(xv.z, sW1[(i+2) * 16 + k2], h1[k2]);
                h1[k2] = fmaf(xv.w, sW1[(i+3) * 16 + k2], h1[k2]);
            }
        }
        #pragma unroll
        for (int k2 = 0; k2 < 16; k2++) h1[k2] = fmaxf(h1[k2], 0.f);

        float h2[8];
        #pragma unroll
        for (int k2 = 0; k2 < 8; k2++) h2[k2] = sb2[k2];
        #pragma unroll
        for (int j = 0; j < 16; j++) {
            const float hj = h1[j];
            #pragma unroll
            for (int k2 = 0; k2 < 8; k2++)
                h2[k2] = fmaf(hj, sW2[j * 8 + k2], h2[k2]);
        }
        float acc = sb3v;
        #pragma unroll
        for (int j = 0; j < 8; j++)
            acc = fmaf(fmaxf(h2[j], 0.f), sW3[j], acc);

        const float s = fmaxf(acc, 0.f) + log1pf(expf(-fabsf(acc)));

        out_w[b * KSEL + lane] = s;
        out_i[b * KSEL + lane] = (float)o;
    }
}

extern "C" void kernel_launch(void* const* d_in, const int* in_sizes, int n_in,
                              void* d_out, int out_size)
{
    const float* x   = (const float*)d_in[0];
    const float* pos = (const float*)d_in[1];
    // d_in[2] = batch (unused; regular layout)
    const float* W1 = (const float*)d_in[3];
    const float* b1 = (const float*)d_in[4];
    const float* W2 = (const float*)d_in[5];
    const float* b2 = (const float*)d_in[6];
    const float* W3 = (const float*)d_in[7];
    const float* b3 = (const float*)d_in[8];

    const int B = in_sizes[2] / NPTS;   // 2048
    float* out_w = (float*)d_out;
    float* out_i = out_w + (size_t)B * KSEL;

    // one-time host-side infra (no device memory involved)
    static cudaStream_t s2 = nullptr;
    static cudaEvent_t evS[NCHUNK];
    static cudaEvent_t evJ = nullptr;
    if (s2 == nullptr) {
        cudaStreamCreateWithFlags(&s2, cudaStreamNonBlocking);
        for (int i = 0; i < NCHUNK; i++)
            cudaEventCreateWithFlags(&evS[i], cudaEventDisableTiming);
        cudaEventCreateWithFlags(&evJ, cudaEventDisableTiming);
    }

    const int CH = B / NCHUNK;   // submaps per chunk
    for (int c = 0; c < NCHUNK; c++) {
        const int b0 = c * CH;
        select_kernel<<<CH, 1024>>>(pos, b0);
        cudaEventRecord(evS[c], 0);
        cudaStreamWaitEvent(s2, evS[c], 0);
        fps_mlp_kernel<<<CH / 2, 128, 0, s2>>>(x, W1, b1, W2, b2, W3, b3,
                                               out_w, out_i, b0);
    }
    cudaEventRecord(evJ, s2);
    cudaStreamWaitEvent(0, evJ, 0);
}

// round 8
// speedup vs baseline: 1.8568x; 1.8568x over previous
#include <cuda_runtime.h>
#include <cuda_bf16.h>

#define NPTS 1024
#define KPOS 512
#define KSEL 32
#define FULLMASK 0xFFFFFFFFu

typedef unsigned long long ull;

// scratch: compacted selected points per submap (x,y,z,idx-bits) + FPS seed slot
__device__ float4 g_pts[2048 * KPOS];
__device__ int    g_seed[2048];

// ---- packed f32x2 helpers (lanewise IEEE rn — bit-identical to scalar rn ops)
__device__ __forceinline__ ull pk2(float a, float b) {
    ull r; asm("mov.b64 %0, {%1, %2};" : "=l"(r) : "f"(a), "f"(b)); return r;
}
__device__ __forceinline__ void upk2(ull v, float& a, float& b) {
    asm("mov.b64 {%0, %1}, %2;" : "=f"(a), "=f"(b) : "l"(v));
}
__device__ __forceinline__ ull addx2(ull a, ull b) {
    ull r; asm("add.rn.f32x2 %0, %1, %2;" : "=l"(r) : "l"(a), "l"(b)); return r;
}
__device__ __forceinline__ ull mulx2(ull a, ull b) {
    ull r; asm("mul.rn.f32x2 %0, %1, %2;" : "=l"(r) : "l"(a), "l"(b)); return r;
}

// ============================================================================
// Kernel 1 (select v3): per-submap selection of the 512 xy-closest points.
// Unique 42-bit key = (dist_bits << 10) | index  ==> top_k(-dist) with jax tie
// semantics reduces to "key <= 512th-smallest-key". One 11-bit histogram pass
// typically suffices; boundary resolved exactly on <=64 candidates; guaranteed
// termination via further passes (keys unique => last pass bins hold 1).
// ============================================================================
__global__ __launch_bounds__(1024, 2)
void select_kernel(const float* __restrict__ pos)
{
    __shared__ unsigned int hist[2048];
    __shared__ ull  sPrefix;
    __shared__ unsigned int sKth, sCnt;
    __shared__ int  sShift;
    __shared__ ull  cand[64];
    __shared__ unsigned int ccnt;
    __shared__ ull  sBound;
    __shared__ unsigned int wA[32];
    __shared__ ull  wpk[32];
    __shared__ ull  spk;

    const int t = threadIdx.x;
    const int w = t >> 5, lane = t & 31;
    const int b = blockIdx.x;
    const long base = (long)b * NPTS;

    if (t == 0) { sPrefix = 0ull; sKth = KPOS; ccnt = 0u; }

    // ---- per-point key: sqrt(px^2+py^2), non-fused (match XLA) ----
    const float px = pos[3*(base+t)+0];
    const float py = pos[3*(base+t)+1];
    const float pz = pos[3*(base+t)+2];
    const unsigned int kb =
        __float_as_uint(__fsqrt_rn(__fadd_rn(__fmul_rn(px,px), __fmul_rn(py,py))));
    const ull key = (((ull)kb) << 10) | (unsigned int)t;   // 42-bit unique key

    // ---- iterative radix narrowing with early exit ----
    {
        const int shifts[4] = {31, 20, 9, 0};
        const int bitsv [4] = {11, 11, 11, 9};
        #pragma unroll 1
        for (int p = 0; p < 4; p++) {
            const int shift = shifts[p];
            hist[t] = 0u; hist[t + 1024] = 0u;
            __syncthreads();
            const ull prefix = sPrefix;
            const unsigned int kth = sKth;
            const ull mhi = ~((1ull << (shift + bitsv[p])) - 1ull);
            const unsigned int dm = (1u << bitsv[p]) - 1u;
            if ((key & mhi) == prefix)
                atomicAdd(&hist[(unsigned int)(key >> shift) & dm], 1u);
            __syncthreads();

            // block prefix over 2048 bins (zeros beyond nb are harmless)
            const unsigned int h0 = hist[2 * t];
            const unsigned int h1 = hist[2 * t + 1];
            const unsigned int s = h0 + h1;
            unsigned int inc = s;
            #pragma unroll
            for (int d = 1; d < 32; d <<= 1) {
                unsigned int v = __shfl_up_sync(FULLMASK, inc, d);
                if (lane >= d) inc += v;
            }
            if (lane == 31) wA[w] = inc;
            __syncthreads();
            if (t < 32) {
                unsigned int wv = wA[t];
                unsigned int winc = wv;
                #pragma unroll
                for (int d = 1; d < 32; d <<= 1) {
                    unsigned int v = __shfl_up_sync(FULLMASK, winc, d);
                    if (t >= d) winc += v;
                }
                wA[t] = winc - wv;
            }
            __syncthreads();
            const unsigned int base0 = wA[w] + (inc - s);
            if (kth > base0 && kth <= base0 + h0) {
                sPrefix = prefix | (((ull)(2 * t)) << shift);
                sKth = kth - base0;
                sCnt = h0;
                sShift = shift;
            } else if (kth > base0 + h0 && kth <= base0 + h0 + h1) {
                sPrefix = prefix | (((ull)(2 * t + 1)) << shift);
                sKth = kth - base0 - h0;
                sCnt = h1;
                sShift = shift;
            }
            __syncthreads();
            if (sCnt <= 64u) break;
        }
    }

    // ---- exact boundary on <=64 candidates ----
    {
        const int fsh = sShift;
        const ull fpre = sPrefix;
        const ull mlo = ~((1ull << fsh) - 1ull);
        if ((key & mlo) == fpre) {
            const unsigned int slot = atomicAdd(&ccnt, 1u);
            cand[slot] = key;
        }
        __syncthreads();
        const unsigned int fcnt = ccnt;      // == sCnt
        const unsigned int fr = sKth;        // 1-based rank within candidates
        if (t < (int)fcnt) {
            const ull mine = cand[t];
            unsigned int rk = 0;
            for (unsigned int j = 0; j < fcnt; j++)
                rk += (cand[j] < mine) ? 1u : 0u;
            if (rk == fr - 1u) sBound = mine;
        }
        __syncthreads();
    }
    const bool sel = (key <= sBound);

    // ---- compaction (slot order == index order) + seed (block-min key) ----
    const unsigned int bal = __ballot_sync(FULLMASK, sel);
    if (lane == 0) wA[w] = __popc(bal);

    ull pk = key;
    #pragma unroll
    for (int off = 16; off > 0; off >>= 1) {
        ull o2 = __shfl_xor_sync(FULLMASK, pk, off);
        if (o2 < pk) pk = o2;
    }
    if (lane == 0) wpk[w] = pk;
    __syncthreads();
    if (t < 32) {
        unsigned int a0 = wA[t];
        unsigned int ia = a0;
        #pragma unroll
        for (int d = 1; d < 32; d <<= 1) {
            unsigned int v = __shfl_up_sync(FULLMASK, ia, d);
            if (t >= d) ia += v;
        }
        wA[t] = ia - a0;

        ull v2 = wpk[t];
        #pragma unroll
        for (int off = 16; off > 0; off >>= 1) {
            ull o2 = __shfl_xor_sync(FULLMASK, v2, off);
            if (o2 < v2) v2 = o2;
        }
        if (t == 0) spk = v2;
    }
    __syncthreads();
    if (sel) {
        const int slot = (int)(wA[w] + __popc(bal & ((1u << lane) - 1u)));
        g_pts[b * KPOS + slot] = make_float4(px, py, pz, __int_as_float(t));
        if (key == spk) g_seed[b] = slot;
    }
}

// ============================================================================
// Kernel 2 (fps v3): ONE warp per submap, 16 pts/lane in registers, packed
// f32x2 distance updates, warp-only argmax (redux.sync), per-lane MLP.
// ============================================================================
__global__ __launch_bounds__(128)
void fps_mlp_kernel(const float* __restrict__ x,
                    const float* __restrict__ W1, const float* __restrict__ b1,
                    const float* __restrict__ W2, const float* __restrict__ b2,
                    const float* __restrict__ W3, const float* __restrict__ b3,
                    float* __restrict__ out_w, float* __restrict__ out_i)
{
    __shared__ float4 qpos[4 * KPOS];
    __shared__ float sW1[512]; __shared__ float sb1[16];
    __shared__ float sW2[128]; __shared__ float sb2[8];
    __shared__ float sW3[8];   __shared__ float sb3v;

    const int tid = threadIdx.x;
    for (int i = tid; i < 512; i += 128) sW1[i] = W1[i];
    if (tid < 128) sW2[tid] = W2[tid];
    if (tid < 16)  sb1[tid] = b1[tid];
    if (tid < 8)   sb2[tid] = b2[tid];
    if (tid < 8)   sW3[tid] = W3[tid];
    if (tid == 0)  sb3v = b3[0];
    __syncthreads();

    const int w = tid >> 5, lane = tid & 31;
    const int b = blockIdx.x * 4 + w;

    const float4* bp = g_pts + (size_t)b * KPOS;
    float4* qp = qpos + w * KPOS;

    ull pxp[8], pyp[8], pzp[8];
    float md[16];
    #pragma unroll
    for (int k = 0; k < 8; k++) {
        const float4 v0 = bp[(2*k)     * 32 + lane];
        const float4 v1 = bp[(2*k + 1) * 32 + lane];
        qp[(2*k)     * 32 + lane] = v0;
        qp[(2*k + 1) * 32 + lane] = v1;
        pxp[k] = pk2(v0.x, v1.x);
        pyp[k] = pk2(v0.y, v1.y);
        pzp[k] = pk2(v0.z, v1.z);
    }
    __syncwarp();

    const int s0 = g_seed[b];
    float4 q = qp[s0];
    int mysel = s0;   // lane 'step' records the step'th selection; step 0 = seed

    {
        const ull qnx = pk2(-q.x, -q.x), qny = pk2(-q.y, -q.y), qnz = pk2(-q.z, -q.z);
        #pragma unroll
        for (int k = 0; k < 8; k++) {
            const ull dx = addx2(pxp[k], qnx);
            const ull dy = addx2(pyp[k], qny);
            const ull dz = addx2(pzp[k], qnz);
            const ull d2 = addx2(addx2(mulx2(dx,dx), mulx2(dy,dy)), mulx2(dz,dz));
            upk2(d2, md[2*k], md[2*k+1]);
        }
    }

    #pragma unroll 1
    for (int step = 1; step < KSEL; step++) {
        // local argmax over 16 owned points (strict > keeps lowest slot)
        float best = md[0]; int bs = lane;
        #pragma unroll
        for (int j = 1; j < 16; j++) {
            const int s = j * 32 + lane;
            if (md[j] > best) { best = md[j]; bs = s; }
        }
        const unsigned int bb = __float_as_uint(best);
        const unsigned int wm = __reduce_max_sync(FULLMASK, bb);
        const unsigned int cand2 = (bb == wm) ? (unsigned int)bs : 0xFFFFFFFFu;
        const int cur = (int)__reduce_min_sync(FULLMASK, cand2);
        if (lane == step) mysel = cur;
        q = qp[cur];
        const ull qnx = pk2(-q.x, -q.x), qny = pk2(-q.y, -q.y), qnz = pk2(-q.z, -q.z);
        #pragma unroll
        for (int k = 0; k < 8; k++) {
            const ull dx = addx2(pxp[k], qnx);
            const ull dy = addx2(pyp[k], qny);
            const ull dz = addx2(pzp[k], qnz);
            const ull d2 = addx2(addx2(mulx2(dx,dx), mulx2(dy,dy)), mulx2(dz,dz));
            float a2, c2;
            upk2(d2, a2, c2);
            md[2*k]   = fminf(md[2*k],   a2);
            md[2*k+1] = fminf(md[2*k+1], c2);
        }
    }

    // ---- per-lane MLP (lane = selection step) ----
    const float4 qs = qp[mysel];
    const int o = __float_as_int(qs.w);
    const float* xr = x + ((long)b * NPTS + o) * 32;

    float h1[16];
    #pragma unroll
    for (int k2 = 0; k2 < 16; k2++) h1[k2] = sb1[k2];
    #pragma unroll
    for (int i = 0; i < 32; i += 4) {
        const float4 xv = *(const float4*)(xr + i);
        #pragma unroll
        for (int k2 = 0; k2 < 16; k2++) {
            h1[k2] = fmaf(xv.x, sW1[(i+0) * 16 + k2], h1[k2]);
            h1[k2] = fmaf(xv.y, sW1[(i+1) * 16 + k2], h1[k2]);
            h1[k2] = fmaf(xv.z, sW1[(i+2) * 16 + k2], h1[k2]);
            h1[k2] = fmaf(xv.w, sW1[(i+3) * 16 + k2], h1[k2]);
        }
    }
    #pragma unroll
    for (int k2 = 0; k2 < 16; k2++) h1[k2] = fmaxf(h1[k2], 0.f);

    float h2[8];
    #pragma unroll
    for (int k2 = 0; k2 < 8; k2++) h2[k2] = sb2[k2];
    #pragma unroll
    for (int j = 0; j < 16; j++) {
        const float hj = h1[j];
        #pragma unroll
        for (int k2 = 0; k2 < 8; k2++)
            h2[k2] = fmaf(hj, sW2[j * 8 + k2], h2[k2]);
    }
    float acc = sb3v;
    #pragma unroll
    for (int j = 0; j < 8; j++)
        acc = fmaf(fmaxf(h2[j], 0.f), sW3[j], acc);

    const float s = fmaxf(acc, 0.f) + log1pf(expf(-fabsf(acc)));

    out_w[b * KSEL + lane] = s;
    out_i[b * KSEL + lane] = (float)o;
}

extern "C" void kernel_launch(void* const* d_in, const int* in_sizes, int n_in,
                              void* d_out, int out_size)
{
    const float* x   = (const float*)d_in[0];
    const float* pos = (const float*)d_in[1];
    // d_in[2] = batch (unused; regular layout)
    const float* W1 = (const float*)d_in[3];
    const float* b1 = (const float*)d_in[4];
    const float* W2 = (const float*)d_in[5];
    const float* b2 = (const float*)d_in[6];
    const float* W3 = (const float*)d_in[7];
    const float* b3 = (const float*)d_in[8];

    const int B = in_sizes[2] / NPTS;   // 2048
    float* out_w = (float*)d_out;
    float* out_i = out_w + (size_t)B * KSEL;

    select_kernel<<<B, 1024>>>(pos);
    fps_mlp_kernel<<<B / 4, 128>>>(x, W1, b1, W2, b2, W3, b3, out_w, out_i);
}

// round 9
// speedup vs baseline: 1.9052x; 1.0261x over previous
#include <cuda_runtime.h>
#include <cuda_bf16.h>

#define NPTS 1024
#define KPOS 512
#define KSEL 32
#define FULLMASK 0xFFFFFFFFu

typedef unsigned long long ull;

// scratch: compacted selected points per submap (x,y,z,idx-bits) + FPS seed slot
__device__ float4 g_pts[2048 * KPOS];
__device__ int    g_seed[2048];

// ---- packed f32x2 helpers (lanewise IEEE rn — bit-identical to scalar rn ops)
__device__ __forceinline__ ull pk2(float a, float b) {
    ull r; asm("mov.b64 %0, {%1, %2};" : "=l"(r) : "f"(a), "f"(b)); return r;
}
__device__ __forceinline__ void upk2(ull v, float& a, float& b) {
    asm("mov.b64 {%0, %1}, %2;" : "=f"(a), "=f"(b) : "l"(v));
}
__device__ __forceinline__ ull addx2(ull a, ull b) {
    ull r; asm("add.rn.f32x2 %0, %1, %2;" : "=l"(r) : "l"(a), "l"(b)); return r;
}
__device__ __forceinline__ ull mulx2(ull a, ull b) {
    ull r; asm("mul.rn.f32x2 %0, %1, %2;" : "=l"(r) : "l"(a), "l"(b)); return r;
}

// ============================================================================
// Kernel 1 (select v4): 512 threads, 2 points/thread. Unique 42-bit key
// (dist_bits<<10 | index); top_k(-dist) with jax tie semantics == key <= bound.
// One 11-bit histogram pass typically; exact boundary on <=64 candidates.
// ============================================================================
__global__ __launch_bounds__(512, 4)
void select_kernel(const float* __restrict__ pos)
{
    __shared__ unsigned int hist[2048];
    __shared__ ull  sPrefix;
    __shared__ unsigned int sKth, sCnt;
    __shared__ int  sShift;
    __shared__ ull  cand[64];
    __shared__ unsigned int ccnt;
    __shared__ ull  sBound;
    __shared__ unsigned int wS[16];
    __shared__ ull  wpk[16];
    __shared__ ull  spk;

    const int t = threadIdx.x;
    const int w = t >> 5, lane = t & 31;
    const int b = blockIdx.x;
    const long base = (long)b * NPTS;

    if (t == 0) { sPrefix = 0ull; sKth = KPOS; ccnt = 0u; }

    // ---- load 2 points (indices 2t, 2t+1) via three float2 (validated R6) ----
    const float2* p2 = (const float2*)(pos + 3 * base + 6 * t);
    const float2 v0 = p2[0], v1 = p2[1], v2 = p2[2];
    const float pxa = v0.x, pya = v0.y, pza = v1.x;
    const float pxb = v1.y, pyb = v2.x, pzb = v2.y;
    const int ia = 2 * t, ib = 2 * t + 1;

    const unsigned int kbA =
        __float_as_uint(__fsqrt_rn(__fadd_rn(__fmul_rn(pxa,pxa), __fmul_rn(pya,pya))));
    const unsigned int kbB =
        __float_as_uint(__fsqrt_rn(__fadd_rn(__fmul_rn(pxb,pxb), __fmul_rn(pyb,pyb))));
    const ull keyA = (((ull)kbA) << 10) | (unsigned int)ia;
    const ull keyB = (((ull)kbB) << 10) | (unsigned int)ib;

    // ---- iterative radix narrowing with early exit ----
    {
        const int shifts[4] = {31, 20, 9, 0};
        const int bitsv [4] = {11, 11, 11, 9};
        #pragma unroll 1
        for (int p = 0; p < 4; p++) {
            const int shift = shifts[p];
            hist[t] = 0u; hist[t + 512] = 0u; hist[t + 1024] = 0u; hist[t + 1536] = 0u;
            __syncthreads();
            const ull prefix = sPrefix;
            const unsigned int kth = sKth;
            const ull mhi = ~((1ull << (shift + bitsv[p])) - 1ull);
            const unsigned int dm = (1u << bitsv[p]) - 1u;
            if ((keyA & mhi) == prefix)
                atomicAdd(&hist[(unsigned int)(keyA >> shift) & dm], 1u);
            if ((keyB & mhi) == prefix)
                atomicAdd(&hist[(unsigned int)(keyB >> shift) & dm], 1u);
            __syncthreads();

            // block prefix over 2048 bins; thread owns bins {4t..4t+3}
            const unsigned int h0 = hist[4*t], h1 = hist[4*t+1],
                               h2 = hist[4*t+2], h3 = hist[4*t+3];
            const unsigned int s = h0 + h1 + h2 + h3;
            unsigned int inc = s;
            #pragma unroll
            for (int d = 1; d < 32; d <<= 1) {
                unsigned int v = __shfl_up_sync(FULLMASK, inc, d);
                if (lane >= d) inc += v;
            }
            if (lane == 31) wS[w] = inc;
            __syncthreads();
            if (t < 32) {
                unsigned int wv = (t < 16) ? wS[t] : 0u;
                unsigned int winc = wv;
                #pragma unroll
                for (int d = 1; d < 32; d <<= 1) {
                    unsigned int v = __shfl_up_sync(FULLMASK, winc, d);
                    if (t >= d) winc += v;
                }
                if (t < 16) wS[t] = winc - wv;
            }
            __syncthreads();
            unsigned int c = wS[w] + (inc - s);
            const unsigned int hv[4] = {h0, h1, h2, h3};
            #pragma unroll
            for (int i = 0; i < 4; i++) {
                if (kth > c && kth <= c + hv[i]) {
                    sPrefix = prefix | (((ull)(4 * t + i)) << shift);
                    sKth = kth - c;
                    sCnt = hv[i];
                    sShift = shift;
                }
                c += hv[i];
            }
            __syncthreads();
            if (sCnt <= 64u) break;
        }
    }

    // ---- exact boundary on <=64 candidates ----
    {
        const int fsh = sShift;
        const ull fpre = sPrefix;
        const ull mlo = ~((1ull << fsh) - 1ull);
        if ((keyA & mlo) == fpre) cand[atomicAdd(&ccnt, 1u)] = keyA;
        if ((keyB & mlo) == fpre) cand[atomicAdd(&ccnt, 1u)] = keyB;
        __syncthreads();
        const unsigned int fcnt = ccnt;
        const unsigned int fr = sKth;
        if (t < (int)fcnt) {
            const ull mine = cand[t];
            unsigned int rk = 0;
            for (unsigned int j = 0; j < fcnt; j++)
                rk += (cand[j] < mine) ? 1u : 0u;
            if (rk == fr - 1u) sBound = mine;
        }
        __syncthreads();
    }
    const bool selA = (keyA <= sBound);
    const bool selB = (keyB <= sBound);

    // ---- compaction (slot order == index order) + seed (block-min key) ----
    const unsigned int balA = __ballot_sync(FULLMASK, selA);
    const unsigned int balB = __ballot_sync(FULLMASK, selB);
    if (lane == 0) wS[w] = __popc(balA) + __popc(balB);

    ull pk = (keyA < keyB) ? keyA : keyB;
    #pragma unroll
    for (int off = 16; off > 0; off >>= 1) {
        ull o2 = __shfl_xor_sync(FULLMASK, pk, off);
        if (o2 < pk) pk = o2;
    }
    if (lane == 0) wpk[w] = pk;
    __syncthreads();
    if (t < 32) {
        unsigned int a0 = (t < 16) ? wS[t] : 0u;
        unsigned int iaW = a0;
        #pragma unroll
        for (int d = 1; d < 32; d <<= 1) {
            unsigned int v = __shfl_up_sync(FULLMASK, iaW, d);
            if (t >= d) iaW += v;
        }
        if (t < 16) wS[t] = iaW - a0;

        ull v2m = (t < 16) ? wpk[t] : ~0ull;
        #pragma unroll
        for (int off = 16; off > 0; off >>= 1) {
            ull o2 = __shfl_xor_sync(FULLMASK, v2m, off);
            if (o2 < v2m) v2m = o2;
        }
        if (t == 0) spk = v2m;
    }
    __syncthreads();
    {
        const unsigned int lm = (1u << lane) - 1u;
        const int baseSlot = (int)(wS[w] + __popc(balA & lm) + __popc(balB & lm));
        if (selA) {
            g_pts[b * KPOS + baseSlot] = make_float4(pxa, pya, pza, __int_as_float(ia));
            if (keyA == spk) g_seed[b] = baseSlot;
        }
        if (selB) {
            const int slotB = baseSlot + (selA ? 1 : 0);
            g_pts[b * KPOS + slotB] = make_float4(pxb, pyb, pzb, __int_as_float(ib));
            if (keyB == spk) g_seed[b] = slotB;
        }
    }
}

// ---- argmax tournament tree: pairs (2i,2i+1) at each level keep left=lower
// slot, so ">=" reproduces exact lowest-slot tie-breaking. Depth 4.
__device__ __forceinline__ void argmax16(const float* md, int lane,
                                         float& best, int& bslot)
{
    float v8[8]; int s8[8];
    #pragma unroll
    for (int i = 0; i < 8; i++) {
        const bool c = md[2*i] >= md[2*i+1];
        v8[i] = c ? md[2*i] : md[2*i+1];
        s8[i] = (c ? (2*i) : (2*i+1)) * 32 + lane;
    }
    float v4[4]; int s4[4];
    #pragma unroll
    for (int i = 0; i < 4; i++) {
        const bool c = v8[2*i] >= v8[2*i+1];
        v4[i] = c ? v8[2*i] : v8[2*i+1];
        s4[i] = c ? s8[2*i] : s8[2*i+1];
    }
    float v2a[2]; int s2a[2];
    #pragma unroll
    for (int i = 0; i < 2; i++) {
        const bool c = v4[2*i] >= v4[2*i+1];
        v2a[i] = c ? v4[2*i] : v4[2*i+1];
        s2a[i] = c ? s4[2*i] : s4[2*i+1];
    }
    const bool c = v2a[0] >= v2a[1];
    best = c ? v2a[0] : v2a[1];
    bslot = c ? s2a[0] : s2a[1];
}

__device__ __forceinline__ float mlp_eval(const float* __restrict__ xr,
                                          const float* sW1, const float* sb1,
                                          const float* sW2, const float* sb2,
                                          const float* sW3, float sb3v)
{
    float h1[16];
    #pragma unroll
    for (int k2 = 0; k2 < 16; k2++) h1[k2] = sb1[k2];
    #pragma unroll
    for (int i = 0; i < 32; i += 4) {
        const float4 xv = *(const float4*)(xr + i);
        #pragma unroll
        for (int k2 = 0; k2 < 16; k2++) {
            h1[k2] = fmaf(xv.x, sW1[(i+0) * 16 + k2], h1[k2]);
            h1[k2] = fmaf(xv.y, sW1[(i+1) * 16 + k2], h1[k2]);
            h1[k2] = fmaf(xv.z, sW1[(i+2) * 16 + k2], h1[k2]);
            h1[k2] = fmaf(xv.w, sW1[(i+3) * 16 + k2], h1[k2]);
        }
    }
    #pragma unroll
    for (int k2 = 0; k2 < 16; k2++) h1[k2] = fmaxf(h1[k2], 0.f);

    float h2[8];
    #pragma unroll
    for (int k2 = 0; k2 < 8; k2++) h2[k2] = sb2[k2];
    #pragma unroll
    for (int j = 0; j < 16; j++) {
        const float hj = h1[j];
        #pragma unroll
        for (int k2 = 0; k2 < 8; k2++)
            h2[k2] = fmaf(hj, sW2[j * 8 + k2], h2[k2]);
    }
    float acc = sb3v;
    #pragma unroll
    for (int j = 0; j < 8; j++)
        acc = fmaf(fmaxf(h2[j], 0.f), sW3[j], acc);

    return fmaxf(acc, 0.f) + log1pf(expf(-fabsf(acc)));
}

// ============================================================================
// Kernel 2 (fps v4): 64-thread CTA; each warp runs TWO submaps interleaved
// (independent dependency chains double in-warp ILP). 16 pts/lane/submap in
// registers, packed f32x2 updates, tournament-tree argmax, per-lane MLP x2.
// ============================================================================
__global__ __launch_bounds__(64)
void fps_mlp_kernel(const float* __restrict__ x,
                    const float* __restrict__ W1, const float* __restrict__ b1,
                    const float* __restrict__ W2, const float* __restrict__ b2,
                    const float* __restrict__ W3, const float* __restrict__ b3,
                    float* __restrict__ out_w, float* __restrict__ out_i)
{
    __shared__ float4 qpos[4 * KPOS];   // 32 KB: [warp*2 + sub][slot]
    __shared__ float sW1[512]; __shared__ float sb1[16];
    __shared__ float sW2[128]; __shared__ float sb2[8];
    __shared__ float sW3[8];   __shared__ float sb3v;

    const int tid = threadIdx.x;
    for (int i = tid; i < 512; i += 64) sW1[i] = W1[i];
    for (int i = tid; i < 128; i += 64) sW2[i] = W2[i];
    if (tid < 16)  sb1[tid] = b1[tid];
    if (tid < 8)   sb2[tid] = b2[tid];
    if (tid < 8)   sW3[tid] = W3[tid];
    if (tid == 0)  sb3v = b3[0];
    __syncthreads();

    const int w = tid >> 5, lane = tid & 31;
    const int bA = blockIdx.x * 4 + w * 2;
    const int bB = bA + 1;

    const float4* gpA = g_pts + (size_t)bA * KPOS;
    const float4* gpB = g_pts + (size_t)bB * KPOS;
    float4* qpA = qpos + (w * 2 + 0) * KPOS;
    float4* qpB = qpos + (w * 2 + 1) * KPOS;

    ull pxA[8], pyA[8], pzA[8], pxB[8], pyB[8], pzB[8];
    float mdA[16], mdB[16];
    #pragma unroll
    for (int k = 0; k < 8; k++) {
        const float4 a0 = gpA[(2*k)     * 32 + lane];
        const float4 a1 = gpA[(2*k + 1) * 32 + lane];
        qpA[(2*k)     * 32 + lane] = a0;
        qpA[(2*k + 1) * 32 + lane] = a1;
        pxA[k] = pk2(a0.x, a1.x); pyA[k] = pk2(a0.y, a1.y); pzA[k] = pk2(a0.z, a1.z);
        const float4 c0 = gpB[(2*k)     * 32 + lane];
        const float4 c1 = gpB[(2*k + 1) * 32 + lane];
        qpB[(2*k)     * 32 + lane] = c0;
        qpB[(2*k + 1) * 32 + lane] = c1;
        pxB[k] = pk2(c0.x, c1.x); pyB[k] = pk2(c0.y, c1.y); pzB[k] = pk2(c0.z, c1.z);
    }
    __syncwarp();

    const int sA0 = g_seed[bA];
    const int sB0 = g_seed[bB];
    float4 qA = qpA[sA0];
    float4 qB = qpB[sB0];
    int myselA = sA0, myselB = sB0;

    {
        const ull ax = pk2(-qA.x, -qA.x), ay = pk2(-qA.y, -qA.y), az = pk2(-qA.z, -qA.z);
        const ull bx = pk2(-qB.x, -qB.x), by = pk2(-qB.y, -qB.y), bz = pk2(-qB.z, -qB.z);
        #pragma unroll
        for (int k = 0; k < 8; k++) {
            const ull dA = addx2(addx2(mulx2(addx2(pxA[k],ax),addx2(pxA[k],ax)),
                                       mulx2(addx2(pyA[k],ay),addx2(pyA[k],ay))),
                                 mulx2(addx2(pzA[k],az),addx2(pzA[k],az)));
            upk2(dA, mdA[2*k], mdA[2*k+1]);
            const ull dB = addx2(addx2(mulx2(addx2(pxB[k],bx),addx2(pxB[k],bx)),
                                       mulx2(addx2(pyB[k],by),addx2(pyB[k],by))),
                                 mulx2(addx2(pzB[k],bz),addx2(pzB[k],bz)));
            upk2(dB, mdB[2*k], mdB[2*k+1]);
        }
    }

    #pragma unroll 1
    for (int step = 1; step < KSEL; step++) {
        float bestA, bestB; int bsA, bsB;
        argmax16(mdA, lane, bestA, bsA);
        argmax16(mdB, lane, bestB, bsB);

        const unsigned int bbA = __float_as_uint(bestA);
        const unsigned int bbB = __float_as_uint(bestB);
        const unsigned int wmA = __reduce_max_sync(FULLMASK, bbA);
        const unsigned int wmB = __reduce_max_sync(FULLMASK, bbB);
        const unsigned int cA = (bbA == wmA) ? (unsigned int)bsA : 0xFFFFFFFFu;
        const unsigned int cB = (bbB == wmB) ? (unsigned int)bsB : 0xFFFFFFFFu;
        const int curA = (int)__reduce_min_sync(FULLMASK, cA);
        const int curB = (int)__reduce_min_sync(FULLMASK, cB);
        if (lane == step) { myselA = curA; myselB = curB; }
        qA = qpA[curA];
        qB = qpB[curB];

        const ull ax = pk2(-qA.x, -qA.x), ay = pk2(-qA.y, -qA.y), az = pk2(-qA.z, -qA.z);
        const ull bx = pk2(-qB.x, -qB.x), by = pk2(-qB.y, -qB.y), bz = pk2(-qB.z, -qB.z);
        #pragma unroll
        for (int k = 0; k < 8; k++) {
            const ull dxA = addx2(pxA[k], ax);
            const ull dyA = addx2(pyA[k], ay);
            const ull dzA = addx2(pzA[k], az);
            const ull d2A = addx2(addx2(mulx2(dxA,dxA), mulx2(dyA,dyA)), mulx2(dzA,dzA));
            const ull dxB = addx2(pxB[k], bx);
            const ull dyB = addx2(pyB[k], by);
            const ull dzB = addx2(pzB[k], bz);
            const ull d2B = addx2(addx2(mulx2(dxB,dxB), mulx2(dyB,dyB)), mulx2(dzB,dzB));
            float a2, c2, e2, f2;
            upk2(d2A, a2, c2);
            upk2(d2B, e2, f2);
            mdA[2*k]   = fminf(mdA[2*k],   a2);
            mdA[2*k+1] = fminf(mdA[2*k+1], c2);
            mdB[2*k]   = fminf(mdB[2*k],   e2);
            mdB[2*k+1] = fminf(mdB[2*k+1], f2);
        }
    }

    // ---- per-lane MLPs (lane = selection step) ----
    {
        const float4 qsA = qpA[myselA];
        const int oA = __float_as_int(qsA.w);
        const float sA = mlp_eval(x + ((long)bA * NPTS + oA) * 32,
                                  sW1, sb1, sW2, sb2, sW3, sb3v);
        out_w[bA * KSEL + lane] = sA;
        out_i[bA * KSEL + lane] = (float)oA;

        const float4 qsB = qpB[myselB];
        const int oB = __float_as_int(qsB.w);
        const float sB = mlp_eval(x + ((long)bB * NPTS + oB) * 32,
                                  sW1, sb1, sW2, sb2, sW3, sb3v);
        out_w[bB * KSEL + lane] = sB;
        out_i[bB * KSEL + lane] = (float)oB;
    }
}

extern "C" void kernel_launch(void* const* d_in, const int* in_sizes, int n_in,
                              void* d_out, int out_size)
{
    const float* x   = (const float*)d_in[0];
    const float* pos = (const float*)d_in[1];
    // d_in[2] = batch (unused; regular layout)
    const float* W1 = (const float*)d_in[3];
    const float* b1 = (const float*)d_in[4];
    const float* W2 = (const float*)d_in[5];
    const float* b2 = (const float*)d_in[6];
    const float* W3 = (const float*)d_in[7];
    const float* b3 = (const float*)d_in[8];

    const int B = in_sizes[2] / NPTS;   // 2048
    float* out_w = (float*)d_out;
    float* out_i = out_w + (size_t)B * KSEL;

    select_kernel<<<B, 512>>>(pos);
    fps_mlp_kernel<<<B / 4, 64>>>(x, W1, b1, W2, b2, W3, b3, out_w, out_i);
}

// round 10
// speedup vs baseline: 2.0735x; 1.0883x over previous
#include <cuda_runtime.h>
#include <cuda_bf16.h>

#define NPTS 1024
#define KPOS 512
#define KSEL 32
#define FULLMASK 0xFFFFFFFFu

typedef unsigned long long ull;

// scratch: compacted selected points per submap (x,y,z,idx-bits) + FPS seed slot
__device__ float4 g_pts[2048 * KPOS];
__device__ int    g_seed[2048];

// ---- packed f32x2 helpers (lanewise IEEE rn — bit-identical to scalar rn ops)
__device__ __forceinline__ ull pk2(float a, float b) {
    ull r; asm("mov.b64 %0, {%1, %2};" : "=l"(r) : "f"(a), "f"(b)); return r;
}
__device__ __forceinline__ void upk2(ull v, float& a, float& b) {
    asm("mov.b64 {%0, %1}, %2;" : "=f"(a), "=f"(b) : "l"(v));
}
__device__ __forceinline__ ull addx2(ull a, ull b) {
    ull r; asm("add.rn.f32x2 %0, %1, %2;" : "=l"(r) : "l"(a), "l"(b)); return r;
}
__device__ __forceinline__ ull mulx2(ull a, ull b) {
    ull r; asm("mul.rn.f32x2 %0, %1, %2;" : "=l"(r) : "l"(a), "l"(b)); return r;
}

// ============================================================================
// Kernel 1 (select v4, measured 24.3us): 512 threads, 2 points/thread.
// Unique 42-bit key (dist_bits<<10 | index); jax top_k(-dist) tie semantics
// == key <= bound. One 11-bit histogram pass typically; exact boundary on
// <=64 candidates; guaranteed termination (keys unique).
// ============================================================================
__global__ __launch_bounds__(512, 4)
void select_kernel(const float* __restrict__ pos)
{
    __shared__ unsigned int hist[2048];
    __shared__ ull  sPrefix;
    __shared__ unsigned int sKth, sCnt;
    __shared__ int  sShift;
    __shared__ ull  cand[64];
    __shared__ unsigned int ccnt;
    __shared__ ull  sBound;
    __shared__ unsigned int wS[16];
    __shared__ ull  wpk[16];
    __shared__ ull  spk;

    const int t = threadIdx.x;
    const int w = t >> 5, lane = t & 31;
    const int b = blockIdx.x;
    const long base = (long)b * NPTS;

    if (t == 0) { sPrefix = 0ull; sKth = KPOS; ccnt = 0u; }

    // ---- load 2 points (indices 2t, 2t+1) via three float2 ----
    const float2* p2 = (const float2*)(pos + 3 * base + 6 * t);
    const float2 v0 = p2[0], v1 = p2[1], v2 = p2[2];
    const float pxa = v0.x, pya = v0.y, pza = v1.x;
    const float pxb = v1.y, pyb = v2.x, pzb = v2.y;
    const int ia = 2 * t, ib = 2 * t + 1;

    const unsigned int kbA =
        __float_as_uint(__fsqrt_rn(__fadd_rn(__fmul_rn(pxa,pxa), __fmul_rn(pya,pya))));
    const unsigned int kbB =
        __float_as_uint(__fsqrt_rn(__fadd_rn(__fmul_rn(pxb,pxb), __fmul_rn(pyb,pyb))));
    const ull keyA = (((ull)kbA) << 10) | (unsigned int)ia;
    const ull keyB = (((ull)kbB) << 10) | (unsigned int)ib;

    // ---- iterative radix narrowing with early exit ----
    {
        const int shifts[4] = {31, 20, 9, 0};
        const int bitsv [4] = {11, 11, 11, 9};
        #pragma unroll 1
        for (int p = 0; p < 4; p++) {
            const int shift = shifts[p];
            hist[t] = 0u; hist[t + 512] = 0u; hist[t + 1024] = 0u; hist[t + 1536] = 0u;
            __syncthreads();
            const ull prefix = sPrefix;
            const unsigned int kth = sKth;
            const ull mhi = ~((1ull << (shift + bitsv[p])) - 1ull);
            const unsigned int dm = (1u << bitsv[p]) - 1u;
            if ((keyA & mhi) == prefix)
                atomicAdd(&hist[(unsigned int)(keyA >> shift) & dm], 1u);
            if ((keyB & mhi) == prefix)
                atomicAdd(&hist[(unsigned int)(keyB >> shift) & dm], 1u);
            __syncthreads();

            const unsigned int h0 = hist[4*t], h1 = hist[4*t+1],
                               h2 = hist[4*t+2], h3 = hist[4*t+3];
            const unsigned int s = h0 + h1 + h2 + h3;
            unsigned int inc = s;
            #pragma unroll
            for (int d = 1; d < 32; d <<= 1) {
                unsigned int v = __shfl_up_sync(FULLMASK, inc, d);
                if (lane >= d) inc += v;
            }
            if (lane == 31) wS[w] = inc;
            __syncthreads();
            if (t < 32) {
                unsigned int wv = (t < 16) ? wS[t] : 0u;
                unsigned int winc = wv;
                #pragma unroll
                for (int d = 1; d < 32; d <<= 1) {
                    unsigned int v = __shfl_up_sync(FULLMASK, winc, d);
                    if (t >= d) winc += v;
                }
                if (t < 16) wS[t] = winc - wv;
            }
            __syncthreads();
            unsigned int c = wS[w] + (inc - s);
            const unsigned int hv[4] = {h0, h1, h2, h3};
            #pragma unroll
            for (int i = 0; i < 4; i++) {
                if (kth > c && kth <= c + hv[i]) {
                    sPrefix = prefix | (((ull)(4 * t + i)) << shift);
                    sKth = kth - c;
                    sCnt = hv[i];
                    sShift = shift;
                }
                c += hv[i];
            }
            __syncthreads();
            if (sCnt <= 64u) break;
        }
    }

    // ---- exact boundary on <=64 candidates ----
    {
        const int fsh = sShift;
        const ull fpre = sPrefix;
        const ull mlo = ~((1ull << fsh) - 1ull);
        if ((keyA & mlo) == fpre) cand[atomicAdd(&ccnt, 1u)] = keyA;
        if ((keyB & mlo) == fpre) cand[atomicAdd(&ccnt, 1u)] = keyB;
        __syncthreads();
        const unsigned int fcnt = ccnt;
        const unsigned int fr = sKth;
        if (t < (int)fcnt) {
            const ull mine = cand[t];
            unsigned int rk = 0;
            for (unsigned int j = 0; j < fcnt; j++)
                rk += (cand[j] < mine) ? 1u : 0u;
            if (rk == fr - 1u) sBound = mine;
        }
        __syncthreads();
    }
    const bool selA = (keyA <= sBound);
    const bool selB = (keyB <= sBound);

    // ---- compaction (slot order == index order) + seed (block-min key) ----
    const unsigned int balA = __ballot_sync(FULLMASK, selA);
    const unsigned int balB = __ballot_sync(FULLMASK, selB);
    if (lane == 0) wS[w] = __popc(balA) + __popc(balB);

    ull pk = (keyA < keyB) ? keyA : keyB;
    #pragma unroll
    for (int off = 16; off > 0; off >>= 1) {
        ull o2 = __shfl_xor_sync(FULLMASK, pk, off);
        if (o2 < pk) pk = o2;
    }
    if (lane == 0) wpk[w] = pk;
    __syncthreads();
    if (t < 32) {
        unsigned int a0 = (t < 16) ? wS[t] : 0u;
        unsigned int iaW = a0;
        #pragma unroll
        for (int d = 1; d < 32; d <<= 1) {
            unsigned int v = __shfl_up_sync(FULLMASK, iaW, d);
            if (t >= d) iaW += v;
        }
        if (t < 16) wS[t] = iaW - a0;

        ull v2m = (t < 16) ? wpk[t] : ~0ull;
        #pragma unroll
        for (int off = 16; off > 0; off >>= 1) {
            ull o2 = __shfl_xor_sync(FULLMASK, v2m, off);
            if (o2 < v2m) v2m = o2;
        }
        if (t == 0) spk = v2m;
    }
    __syncthreads();
    {
        const unsigned int lm = (1u << lane) - 1u;
        const int baseSlot = (int)(wS[w] + __popc(balA & lm) + __popc(balB & lm));
        if (selA) {
            g_pts[b * KPOS + baseSlot] = make_float4(pxa, pya, pza, __int_as_float(ia));
            if (keyA == spk) g_seed[b] = baseSlot;
        }
        if (selB) {
            const int slotB = baseSlot + (selA ? 1 : 0);
            g_pts[b * KPOS + slotB] = make_float4(pxb, pyb, pzb, __int_as_float(ib));
            if (keyB == spk) g_seed[b] = slotB;
        }
    }
}

// ---- argmax tournament tree (validated bit-exact in R9): pairs (2i,2i+1)
// keep left=lower slot at every level, so ">=" reproduces exact lowest-slot
// tie-breaking. Depth 4 instead of a 16-deep dependent chain.
__device__ __forceinline__ void argmax16(const float* md, int lane,
                                         float& best, int& bslot)
{
    float v8[8]; int s8[8];
    #pragma unroll
    for (int i = 0; i < 8; i++) {
        const bool c = md[2*i] >= md[2*i+1];
        v8[i] = c ? md[2*i] : md[2*i+1];
        s8[i] = (c ? (2*i) : (2*i+1)) * 32 + lane;
    }
    float v4[4]; int s4[4];
    #pragma unroll
    for (int i = 0; i < 4; i++) {
        const bool c = v8[2*i] >= v8[2*i+1];
        v4[i] = c ? v8[2*i] : v8[2*i+1];
        s4[i] = c ? s8[2*i] : s8[2*i+1];
    }
    float v2a[2]; int s2a[2];
    #pragma unroll
    for (int i = 0; i < 2; i++) {
        const bool c = v4[2*i] >= v4[2*i+1];
        v2a[i] = c ? v4[2*i] : v4[2*i+1];
        s2a[i] = c ? s4[2*i] : s4[2*i+1];
    }
    const bool c = v2a[0] >= v2a[1];
    best = c ? v2a[0] : v2a[1];
    bslot = c ? s2a[0] : s2a[1];
}

// ============================================================================
// Kernel 2 (fps v5 = v3 structure + tournament argmax): ONE warp per submap,
// 16 pts/lane in registers, packed f32x2 updates, redux argmax, per-lane MLP.
// ============================================================================
__global__ __launch_bounds__(128)
void fps_mlp_kernel(const float* __restrict__ x,
                    const float* __restrict__ W1, const float* __restrict__ b1,
                    const float* __restrict__ W2, const float* __restrict__ b2,
                    const float* __restrict__ W3, const float* __restrict__ b3,
                    float* __restrict__ out_w, float* __restrict__ out_i)
{
    __shared__ float4 qpos[4 * KPOS];
    __shared__ float sW1[512]; __shared__ float sb1[16];
    __shared__ float sW2[128]; __shared__ float sb2[8];
    __shared__ float sW3[8];   __shared__ float sb3v;

    const int tid = threadIdx.x;
    for (int i = tid; i < 512; i += 128) sW1[i] = W1[i];
    if (tid < 128) sW2[tid] = W2[tid];
    if (tid < 16)  sb1[tid] = b1[tid];
    if (tid < 8)   sb2[tid] = b2[tid];
    if (tid < 8)   sW3[tid] = W3[tid];
    if (tid == 0)  sb3v = b3[0];
    __syncthreads();

    const int w = tid >> 5, lane = tid & 31;
    const int b = blockIdx.x * 4 + w;

    const float4* bp = g_pts + (size_t)b * KPOS;
    float4* qp = qpos + w * KPOS;

    ull pxp[8], pyp[8], pzp[8];
    float md[16];
    #pragma unroll
    for (int k = 0; k < 8; k++) {
        const float4 v0 = bp[(2*k)     * 32 + lane];
        const float4 v1 = bp[(2*k + 1) * 32 + lane];
        qp[(2*k)     * 32 + lane] = v0;
        qp[(2*k + 1) * 32 + lane] = v1;
        pxp[k] = pk2(v0.x, v1.x);
        pyp[k] = pk2(v0.y, v1.y);
        pzp[k] = pk2(v0.z, v1.z);
    }
    __syncwarp();

    const int s0 = g_seed[b];
    float4 q = qp[s0];
    int mysel = s0;   // lane 'step' records the step'th selection; step 0 = seed

    {
        const ull qnx = pk2(-q.x, -q.x), qny = pk2(-q.y, -q.y), qnz = pk2(-q.z, -q.z);
        #pragma unroll
        for (int k = 0; k < 8; k++) {
            const ull dx = addx2(pxp[k], qnx);
            const ull dy = addx2(pyp[k], qny);
            const ull dz = addx2(pzp[k], qnz);
            const ull d2 = addx2(addx2(mulx2(dx,dx), mulx2(dy,dy)), mulx2(dz,dz));
            upk2(d2, md[2*k], md[2*k+1]);
        }
    }

    #pragma unroll 1
    for (int step = 1; step < KSEL; step++) {
        float best; int bs;
        argmax16(md, lane, best, bs);
        const unsigned int bb = __float_as_uint(best);
        const unsigned int wm = __reduce_max_sync(FULLMASK, bb);
        const unsigned int cand2 = (bb == wm) ? (unsigned int)bs : 0xFFFFFFFFu;
        const int cur = (int)__reduce_min_sync(FULLMASK, cand2);
        if (lane == step) mysel = cur;
        q = qp[cur];
        const ull qnx = pk2(-q.x, -q.x), qny = pk2(-q.y, -q.y), qnz = pk2(-q.z, -q.z);
        #pragma unroll
        for (int k = 0; k < 8; k++) {
            const ull dx = addx2(pxp[k], qnx);
            const ull dy = addx2(pyp[k], qny);
            const ull dz = addx2(pzp[k], qnz);
            const ull d2 = addx2(addx2(mulx2(dx,dx), mulx2(dy,dy)), mulx2(dz,dz));
            float a2, c2;
            upk2(d2, a2, c2);
            md[2*k]   = fminf(md[2*k],   a2);
            md[2*k+1] = fminf(md[2*k+1], c2);
        }
    }

    // ---- per-lane MLP (lane = selection step) ----
    const float4 qs = qp[mysel];
    const int o = __float_as_int(qs.w);
    const float* xr = x + ((long)b * NPTS + o) * 32;

    float h1[16];
    #pragma unroll
    for (int k2 = 0; k2 < 16; k2++) h1[k2] = sb1[k2];
    #pragma unroll
    for (int i = 0; i < 32; i += 4) {
        const float4 xv = *(const float4*)(xr + i);
        #pragma unroll
        for (int k2 = 0; k2 < 16; k2++) {
            h1[k2] = fmaf(xv.x, sW1[(i+0) * 16 + k2], h1[k2]);
            h1[k2] = fmaf(xv.y, sW1[(i+1) * 16 + k2], h1[k2]);
            h1[k2] = fmaf(xv.z, sW1[(i+2) * 16 + k2], h1[k2]);
            h1[k2] = fmaf(xv.w, sW1[(i+3) * 16 + k2], h1[k2]);
        }
    }
    #pragma unroll
    for (int k2 = 0; k2 < 16; k2++) h1[k2] = fmaxf(h1[k2], 0.f);

    float h2[8];
    #pragma unroll
    for (int k2 = 0; k2 < 8; k2++) h2[k2] = sb2[k2];
    #pragma unroll
    for (int j = 0; j < 16; j++) {
        const float hj = h1[j];
        #pragma unroll
        for (int k2 = 0; k2 < 8; k2++)
            h2[k2] = fmaf(hj, sW2[j * 8 + k2], h2[k2]);
    }
    float acc = sb3v;
    #pragma unroll
    for (int j = 0; j < 8; j++)
        acc = fmaf(fmaxf(h2[j], 0.f), sW3[j], acc);

    const float s = fmaxf(acc, 0.f) + log1pf(expf(-fabsf(acc)));

    out_w[b * KSEL + lane] = s;
    out_i[b * KSEL + lane] = (float)o;
}

extern "C" void kernel_launch(void* const* d_in, const int* in_sizes, int n_in,
                              void* d_out, int out_size)
{
    const float* x   = (const float*)d_in[0];
    const float* pos = (const float*)d_in[1];
    // d_in[2] = batch (unused; regular layout)
    const float* W1 = (const float*)d_in[3];
    const float* b1 = (const float*)d_in[4];
    const float* W2 = (const float*)d_in[5];
    const float* b2 = (const float*)d_in[6];
    const float* W3 = (const float*)d_in[7];
    const float* b3 = (const float*)d_in[8];

    const int B = in_sizes[2] / NPTS;   // 2048
    float* out_w = (float*)d_out;
    float* out_i = out_w + (size_t)B * KSEL;

    select_kernel<<<B, 512>>>(pos);
    fps_mlp_kernel<<<B / 4, 128>>>(x, W1, b1, W2, b2, W3, b3, out_w, out_i);
}